// round 1
// baseline (speedup 1.0000x reference)
#include <cuda_runtime.h>
#include <cuda_bf16.h>
#include <cstdint>

// Problem constants
#define B 32
#define P 196
#define D 512
#define H 8
#define U 4
#define C 500

#define D4 128            // D / 4 (float4)
#define TOK_K 11          // known prompt tokens: pre, dom, sem(8), suf
#define TOK_U 7           // unknown prompt tokens: pre, dom, usem(4), suf

// Output slice offsets (floats), tuple order: known_prompts, unknown_prompts, semantic_tokens
#define OUT_KNOWN 0LL
#define N_KNOWN   (16000LL * TOK_K * D)        // 90,112,000
#define OUT_UNK   (N_KNOWN)
#define N_UNK     ((long long)B * TOK_U * D)   // 114,688
#define OUT_SEM   (OUT_UNK + N_UNK)            // 90,226,688

// Scratch (device globals — no allocations allowed)
__device__ float g_scores[B * P * H];      // [b][p][h]
__device__ float g_dom[B * D];             // projected_domain
__device__ float g_psem[B * H * D];        // projected_sem

// ---------------------------------------------------------------------------
// K1: scores[b][p][h] = dot(patch[b][p], query[h]); grid = B*P, block = 256
// ---------------------------------------------------------------------------
__global__ void k_scores(const float* __restrict__ patch,
                         const float* __restrict__ query) {
    int bp = blockIdx.x;                  // b*P + p
    int w = threadIdx.x >> 5, lane = threadIdx.x & 31;   // warp == head
    const float* row = patch + (size_t)bp * D;
    const float* q = query + (size_t)w * D;
    float acc = 0.f;
    #pragma unroll 4
    for (int d = lane; d < D; d += 32) acc = fmaf(row[d], q[d], acc);
    #pragma unroll
    for (int o = 16; o; o >>= 1) acc += __shfl_xor_sync(0xffffffffu, acc, o);
    if (lane == 0) g_scores[(size_t)bp * H + w] = acc;
}

// ---------------------------------------------------------------------------
// K2: softmax over p (per b,h) then semantic_tokens[b][h][d]; grid = B, block = 512
// Writes semantic tokens directly into the output slice.
// ---------------------------------------------------------------------------
__global__ void k_tokens(const float* __restrict__ patch,
                         float* __restrict__ out_sem) {
    __shared__ float sw[P][H + 1];        // +1 pad to kill 4-way bank conflicts
    int b = blockIdx.x, tid = threadIdx.x;
    for (int i = tid; i < P * H; i += 512) {
        int p = i / H, h = i - p * H;
        sw[p][h] = g_scores[(size_t)b * P * H + i];
    }
    __syncthreads();

    int w = tid >> 5, lane = tid & 31;
    if (w < H) {
        int h = w;
        float mx = -3.4e38f;
        for (int p = lane; p < P; p += 32) mx = fmaxf(mx, sw[p][h]);
        #pragma unroll
        for (int o = 16; o; o >>= 1) mx = fmaxf(mx, __shfl_xor_sync(0xffffffffu, mx, o));
        float sum = 0.f;
        for (int p = lane; p < P; p += 32) {
            float e = expf(sw[p][h] - mx);
            sw[p][h] = e;
            sum += e;
        }
        #pragma unroll
        for (int o = 16; o; o >>= 1) sum += __shfl_xor_sync(0xffffffffu, sum, o);
        float inv = 1.f / sum;
        for (int p = lane; p < P; p += 32) sw[p][h] *= inv;
    }
    __syncthreads();

    int d = tid;  // 0..511, coalesced patch reads across the warp
    float acc[H];
    #pragma unroll
    for (int h = 0; h < H; h++) acc[h] = 0.f;
    const float* pb = patch + (size_t)b * P * D + d;
    for (int p = 0; p < P; p++) {
        float x = pb[(size_t)p * D];
        #pragma unroll
        for (int h = 0; h < H; h++) acc[h] = fmaf(sw[p][h], x, acc[h]);
    }
    #pragma unroll
    for (int h = 0; h < H; h++)
        out_sem[((size_t)b * H + h) * D + d] = acc[h];
}

// ---------------------------------------------------------------------------
// K3: projected_domain[b][e] = dot(G[b], dom_W[e]) + dom_b[e]; grid = B, block = 512
// ---------------------------------------------------------------------------
__global__ void k_dom(const float* __restrict__ G,
                      const float* __restrict__ W,
                      const float* __restrict__ bias) {
    __shared__ float gs[D];
    int b = blockIdx.x, tid = threadIdx.x;
    gs[tid] = G[(size_t)b * D + tid];
    __syncthreads();
    int w = tid >> 5, lane = tid & 31;
    // 16 warps x 32 e's each
    for (int i = 0; i < 32; i++) {
        int e = w * 32 + i;
        const float* wr = W + (size_t)e * D;
        float acc = 0.f;
        #pragma unroll 4
        for (int d = lane; d < D; d += 32) acc = fmaf(wr[d], gs[d], acc);
        #pragma unroll
        for (int o = 16; o; o >>= 1) acc += __shfl_xor_sync(0xffffffffu, acc, o);
        if (lane == 0) g_dom[(size_t)b * D + e] = acc + bias[e];
    }
}

// ---------------------------------------------------------------------------
// K4: projected_sem[b][h][e] = dot(S[b][h], sem_W[h][e]) + sem_b[h][e]
// grid = (64 e-chunks, H, 2 b-groups of 16), block = 256 (warp per e)
// ---------------------------------------------------------------------------
__global__ void k_sem(const float* __restrict__ S,    // semantic tokens slice
                      const float* __restrict__ W,
                      const float* __restrict__ bias) {
    __shared__ float ss[16][D];           // 32 KB
    int ec = blockIdx.x, h = blockIdx.y, b0 = blockIdx.z * 16;
    int tid = threadIdx.x, w = tid >> 5, lane = tid & 31;
    for (int i = tid; i < 16 * D; i += 256) {
        int bi = i >> 9, d = i & 511;
        ss[bi][d] = S[(((size_t)(b0 + bi)) * H + h) * D + d];
    }
    __syncthreads();
    int e = ec * 8 + w;
    const float* wr = W + ((size_t)h * D + e) * D;
    float wreg[16];
    #pragma unroll
    for (int k = 0; k < 16; k++) wreg[k] = wr[lane + 32 * k];
    float bv = bias[(size_t)h * D + e];
    for (int bi = 0; bi < 16; bi++) {
        float acc = 0.f;
        #pragma unroll
        for (int k = 0; k < 16; k++) acc = fmaf(wreg[k], ss[bi][lane + 32 * k], acc);
        #pragma unroll
        for (int o = 16; o; o >>= 1) acc += __shfl_xor_sync(0xffffffffu, acc, o);
        if (lane == 0)
            g_psem[(((size_t)(b0 + bi)) * H + h) * D + e] = acc + bv;
    }
}

// ---------------------------------------------------------------------------
// K5: known_prompts — the 360 MB broadcast write. float4 grid-stride,
// streaming stores; sources all L2-resident.
// ---------------------------------------------------------------------------
__global__ void k_known(const float4* __restrict__ pre,
                        const float4* __restrict__ suf,
                        float4* __restrict__ out) {
    const float4* dom = (const float4*)g_dom;
    const float4* sem = (const float4*)g_psem;
    const long long N4 = 16000LL * TOK_K * D4;   // 22,528,000
    long long stride = (long long)gridDim.x * blockDim.x;
    for (long long i = (long long)blockIdx.x * blockDim.x + threadIdx.x;
         i < N4; i += stride) {
        int d4 = (int)(i & (D4 - 1));
        long long r = i >> 7;                 // bc*11 + t
        int t = (int)(r % TOK_K);
        int bc = (int)(r / TOK_K);
        int c = bc % C;
        int b = bc / C;
        float4 v;
        if (t == 0)       v = __ldg(&pre[(size_t)c * D4 + d4]);
        else if (t == 10) v = __ldg(&suf[(size_t)c * D4 + d4]);
        else if (t == 1)  v = __ldg(&dom[(size_t)b * D4 + d4]);
        else              v = __ldg(&sem[((size_t)b * H + (t - 2)) * D4 + d4]);
        __stcs(&out[i], v);
    }
}

// ---------------------------------------------------------------------------
// K6: unknown_prompts (32, 7, 512)
// ---------------------------------------------------------------------------
__global__ void k_unknown(const float4* __restrict__ upre,
                          const float4* __restrict__ usuf,
                          const float4* __restrict__ ust,
                          float4* __restrict__ out) {
    const float4* dom = (const float4*)g_dom;
    const int N4 = B * TOK_U * D4;           // 28,672
    for (int i = blockIdx.x * blockDim.x + threadIdx.x; i < N4;
         i += gridDim.x * blockDim.x) {
        int d4 = i & (D4 - 1);
        int r = i >> 7;                       // b*7 + t
        int t = r % TOK_U;
        int b = r / TOK_U;
        float4 v;
        if (t == 0)      v = upre[d4];
        else if (t == 6) v = usuf[d4];
        else if (t == 1) v = dom[(size_t)b * D4 + d4];
        else             v = ust[(size_t)(t - 2) * D4 + d4];
        out[i] = v;
    }
}

extern "C" void kernel_launch(void* const* d_in, const int* in_sizes, int n_in,
                              void* d_out, int out_size) {
    const float* patch = (const float*)d_in[0];   // (B,P,D)
    const float* gfeat = (const float*)d_in[1];   // (B,D)
    const float* query = (const float*)d_in[2];   // (H,D)
    const float* domW  = (const float*)d_in[3];   // (D,D)
    const float* domb  = (const float*)d_in[4];   // (D,)
    const float* semW  = (const float*)d_in[5];   // (H,D,D)
    const float* semb  = (const float*)d_in[6];   // (H,D)
    const float* ust   = (const float*)d_in[7];   // (U,D)
    const float* kpre  = (const float*)d_in[8];   // (C,1,D)
    const float* ksuf  = (const float*)d_in[9];   // (C,1,D)
    const float* upre  = (const float*)d_in[10];  // (1,D)
    const float* usuf  = (const float*)d_in[11];  // (1,D)

    float* out = (float*)d_out;
    float* out_known = out + OUT_KNOWN;
    float* out_unk   = out + OUT_UNK;
    float* out_sem   = out + OUT_SEM;

    // 1. attention scores
    k_scores<<<B * P, 256>>>(patch, query);
    // 2. softmax + semantic tokens (written straight to output slice)
    k_tokens<<<B, 512>>>(patch, out_sem);
    // 3. domain projection
    k_dom<<<B, 512>>>(gfeat, domW, domb);
    // 4. semantic projection (reads tokens from output slice)
    k_sem<<<dim3(64, H, 2), 256>>>(out_sem, semW, semb);
    // 5. big broadcast write (360 MB)
    k_known<<<2368, 512>>>((const float4*)kpre, (const float4*)ksuf,
                           (float4*)out_known);
    // 6. unknown prompts
    k_unknown<<<56, 512>>>((const float4*)upre, (const float4*)usuf,
                           (const float4*)ust, (float4*)out_unk);
}

// round 2
// speedup vs baseline: 1.1160x; 1.1160x over previous
#include <cuda_runtime.h>
#include <cuda_bf16.h>
#include <cstdint>

// Problem constants
#define B 32
#define P 196
#define D 512
#define H 8
#define U 4
#define C 500

#define D4 128            // D / 4 (float4)
#define TOK_K 11          // known prompt tokens: pre, dom, sem(8), suf
#define TOK_U 7           // unknown prompt tokens: pre, dom, usem(4), suf

// Output slice offsets (floats), tuple order: known_prompts, unknown_prompts, semantic_tokens
#define N_KNOWN   (16000LL * TOK_K * D)        // 90,112,000
#define OUT_UNK   (N_KNOWN)
#define N_UNK     ((long long)B * TOK_U * D)   // 114,688
#define OUT_SEM   (OUT_UNK + N_UNK)            // 90,226,688

// Scratch (device globals — no allocations allowed)
__device__ float g_scores[B * P * H];      // [b][p][h]
__device__ float g_dom[B * D];             // projected_domain
__device__ float g_psem[B * H * D];        // projected_sem

// ---------------------------------------------------------------------------
// K1: scores[b][p][h] = dot(patch[b][p], query[h]); grid = B*P, block = 256
// float4 loads: 4 vec-iterations per lane.
// ---------------------------------------------------------------------------
__global__ void k_scores(const float4* __restrict__ patch,
                         const float4* __restrict__ query) {
    int bp = blockIdx.x;                  // b*P + p
    int w = threadIdx.x >> 5, lane = threadIdx.x & 31;   // warp == head
    const float4* row = patch + (size_t)bp * D4;
    const float4* q = query + (size_t)w * D4;
    float acc = 0.f;
    #pragma unroll
    for (int k = 0; k < 4; k++) {
        float4 r = row[lane + 32 * k];
        float4 qq = q[lane + 32 * k];
        acc = fmaf(r.x, qq.x, acc);
        acc = fmaf(r.y, qq.y, acc);
        acc = fmaf(r.z, qq.z, acc);
        acc = fmaf(r.w, qq.w, acc);
    }
    #pragma unroll
    for (int o = 16; o; o >>= 1) acc += __shfl_xor_sync(0xffffffffu, acc, o);
    if (lane == 0) g_scores[(size_t)bp * H + w] = acc;
}

// ---------------------------------------------------------------------------
// K2: softmax over p (per b,h) then semantic_tokens[b][h][d]
// grid = (B, 4) d-chunks of 128; block = 128. Softmax recomputed per block.
// ---------------------------------------------------------------------------
__global__ void k_tokens(const float* __restrict__ patch,
                         float* __restrict__ out_sem) {
    __shared__ float sw[P][H + 1];        // pad: conflict-free softmax column walk
    int b = blockIdx.x, dc = blockIdx.y;
    int tid = threadIdx.x;
    for (int i = tid; i < P * H; i += 128) {
        int p = i >> 3, h = i & 7;
        sw[p][h] = g_scores[(size_t)b * P * H + i];
    }
    __syncthreads();

    int w = tid >> 5, lane = tid & 31;
    for (int h = w; h < H; h += 4) {      // 4 warps, 2 heads each
        float mx = -3.4e38f;
        for (int p = lane; p < P; p += 32) mx = fmaxf(mx, sw[p][h]);
        #pragma unroll
        for (int o = 16; o; o >>= 1) mx = fmaxf(mx, __shfl_xor_sync(0xffffffffu, mx, o));
        float sum = 0.f;
        for (int p = lane; p < P; p += 32) {
            float e = expf(sw[p][h] - mx);
            sw[p][h] = e;
            sum += e;
        }
        #pragma unroll
        for (int o = 16; o; o >>= 1) sum += __shfl_xor_sync(0xffffffffu, sum, o);
        float inv = 1.f / sum;
        for (int p = lane; p < P; p += 32) sw[p][h] *= inv;
    }
    __syncthreads();

    int d = dc * 128 + tid;
    float acc[H];
    #pragma unroll
    for (int h = 0; h < H; h++) acc[h] = 0.f;
    const float* pb = patch + (size_t)b * P * D + d;
    #pragma unroll 4
    for (int p = 0; p < P; p++) {
        float x = pb[(size_t)p * D];
        #pragma unroll
        for (int h = 0; h < H; h++) acc[h] = fmaf(sw[p][h], x, acc[h]);
    }
    #pragma unroll
    for (int h = 0; h < H; h++)
        out_sem[((size_t)b * H + h) * D + d] = acc[h];
}

// ---------------------------------------------------------------------------
// K3: projected_domain[b][e] = dot(G[b], dom_W[e]) + dom_b[e]; grid = B, block = 512
// ---------------------------------------------------------------------------
__global__ void k_dom(const float* __restrict__ G,
                      const float* __restrict__ W,
                      const float* __restrict__ bias) {
    __shared__ float gs[D];
    int b = blockIdx.x, tid = threadIdx.x;
    gs[tid] = G[(size_t)b * D + tid];
    __syncthreads();
    int w = tid >> 5, lane = tid & 31;
    // 16 warps x 8 groups of 4 e's (interleaved reductions)
    for (int g = 0; g < 8; g++) {
        int e = w * 32 + g * 4;
        float a0 = 0.f, a1 = 0.f, a2 = 0.f, a3 = 0.f;
        const float* w0 = W + (size_t)(e + 0) * D;
        const float* w1 = W + (size_t)(e + 1) * D;
        const float* w2 = W + (size_t)(e + 2) * D;
        const float* w3 = W + (size_t)(e + 3) * D;
        #pragma unroll 4
        for (int d = lane; d < D; d += 32) {
            float x = gs[d];
            a0 = fmaf(w0[d], x, a0);
            a1 = fmaf(w1[d], x, a1);
            a2 = fmaf(w2[d], x, a2);
            a3 = fmaf(w3[d], x, a3);
        }
        #pragma unroll
        for (int o = 16; o; o >>= 1) {
            a0 += __shfl_xor_sync(0xffffffffu, a0, o);
            a1 += __shfl_xor_sync(0xffffffffu, a1, o);
            a2 += __shfl_xor_sync(0xffffffffu, a2, o);
            a3 += __shfl_xor_sync(0xffffffffu, a3, o);
        }
        if (lane == 0) {
            g_dom[(size_t)b * D + e + 0] = a0 + bias[e + 0];
            g_dom[(size_t)b * D + e + 1] = a1 + bias[e + 1];
            g_dom[(size_t)b * D + e + 2] = a2 + bias[e + 2];
            g_dom[(size_t)b * D + e + 3] = a3 + bias[e + 3];
        }
    }
}

// ---------------------------------------------------------------------------
// K4: projected_sem[b][h][e] = dot(S[b][h], sem_W[h][e]) + sem_b[h][e]
// grid = (64 e-chunks, H, 2 b-groups of 16), block = 256 (warp per e).
// bi processed in groups of 4: the four shuffle-reduction trees interleave,
// hiding the 26-cycle SHFL latency 4x.
// ---------------------------------------------------------------------------
__global__ void k_sem(const float* __restrict__ S,    // semantic tokens slice
                      const float* __restrict__ W,
                      const float* __restrict__ bias) {
    __shared__ float ss[16][D];           // 32 KB
    int ec = blockIdx.x, h = blockIdx.y, b0 = blockIdx.z * 16;
    int tid = threadIdx.x, w = tid >> 5, lane = tid & 31;
    for (int i = tid; i < 16 * D; i += 256) {
        int bi = i >> 9, d = i & 511;
        ss[bi][d] = S[(((size_t)(b0 + bi)) * H + h) * D + d];
    }
    __syncthreads();
    int e = ec * 8 + w;
    const float* wr = W + ((size_t)h * D + e) * D;
    float wreg[16];
    #pragma unroll
    for (int k = 0; k < 16; k++) wreg[k] = wr[lane + 32 * k];
    float bv = bias[(size_t)h * D + e];
    for (int bg = 0; bg < 16; bg += 4) {
        float a0 = 0.f, a1 = 0.f, a2 = 0.f, a3 = 0.f;
        #pragma unroll
        for (int k = 0; k < 16; k++) {
            int idx = lane + 32 * k;
            a0 = fmaf(wreg[k], ss[bg + 0][idx], a0);
            a1 = fmaf(wreg[k], ss[bg + 1][idx], a1);
            a2 = fmaf(wreg[k], ss[bg + 2][idx], a2);
            a3 = fmaf(wreg[k], ss[bg + 3][idx], a3);
        }
        #pragma unroll
        for (int o = 16; o; o >>= 1) {
            a0 += __shfl_xor_sync(0xffffffffu, a0, o);
            a1 += __shfl_xor_sync(0xffffffffu, a1, o);
            a2 += __shfl_xor_sync(0xffffffffu, a2, o);
            a3 += __shfl_xor_sync(0xffffffffu, a3, o);
        }
        if (lane == 0) {
            g_psem[(((size_t)(b0 + bg + 0)) * H + h) * D + e] = a0 + bv;
            g_psem[(((size_t)(b0 + bg + 1)) * H + h) * D + e] = a1 + bv;
            g_psem[(((size_t)(b0 + bg + 2)) * H + h) * D + e] = a2 + bv;
            g_psem[(((size_t)(b0 + bg + 3)) * H + h) * D + e] = a3 + bv;
        }
    }
}

// ---------------------------------------------------------------------------
// K5: prompt fill — one block per prompt row. Blocks [0,16000) write
// known_prompts row bc; blocks [16000,16032) write unknown_prompts row b.
// Token id = i>>7 (power of 2 -> cheap, warp-uniform since 128 f4/token).
// Streaming stores: 360 MB write-once, keep out of L2 working set.
// ---------------------------------------------------------------------------
__global__ void k_fill(const float4* __restrict__ pre,
                       const float4* __restrict__ suf,
                       const float4* __restrict__ upre,
                       const float4* __restrict__ usuf,
                       const float4* __restrict__ ust,
                       float4* __restrict__ out_known,
                       float4* __restrict__ out_unk) {
    int bc = blockIdx.x;
    if (bc < 16000) {
        int b = bc / C, c = bc - b * C;
        const float4* dom = ((const float4*)g_dom) + (size_t)b * D4;
        const float4* sem = ((const float4*)g_psem) + (size_t)b * H * D4;
        const float4* pr = pre + (size_t)c * D4;
        const float4* su = suf + (size_t)c * D4;
        float4* o = out_known + (size_t)bc * TOK_K * D4;
        for (int i = threadIdx.x; i < TOK_K * D4; i += blockDim.x) {
            int t = i >> 7, d4 = i & (D4 - 1);
            float4 v;
            if (t == 0)       v = __ldg(&pr[d4]);
            else if (t == 1)  v = __ldg(&dom[d4]);
            else if (t == 10) v = __ldg(&su[d4]);
            else              v = __ldg(&sem[(size_t)(t - 2) * D4 + d4]);
            __stcs(&o[i], v);
        }
    } else {
        int b = bc - 16000;
        const float4* dom = ((const float4*)g_dom) + (size_t)b * D4;
        float4* o = out_unk + (size_t)b * TOK_U * D4;
        for (int i = threadIdx.x; i < TOK_U * D4; i += blockDim.x) {
            int t = i >> 7, d4 = i & (D4 - 1);
            float4 v;
            if (t == 0)      v = __ldg(&upre[d4]);
            else if (t == 1) v = __ldg(&dom[d4]);
            else if (t == 6) v = __ldg(&usuf[d4]);
            else             v = __ldg(&ust[(size_t)(t - 2) * D4 + d4]);
            o[i] = v;
        }
    }
}

extern "C" void kernel_launch(void* const* d_in, const int* in_sizes, int n_in,
                              void* d_out, int out_size) {
    const float* patch = (const float*)d_in[0];   // (B,P,D)
    const float* gfeat = (const float*)d_in[1];   // (B,D)
    const float* query = (const float*)d_in[2];   // (H,D)
    const float* domW  = (const float*)d_in[3];   // (D,D)
    const float* domb  = (const float*)d_in[4];   // (D,)
    const float* semW  = (const float*)d_in[5];   // (H,D,D)
    const float* semb  = (const float*)d_in[6];   // (H,D)
    const float* ust   = (const float*)d_in[7];   // (U,D)
    const float* kpre  = (const float*)d_in[8];   // (C,1,D)
    const float* ksuf  = (const float*)d_in[9];   // (C,1,D)
    const float* upre  = (const float*)d_in[10];  // (1,D)
    const float* usuf  = (const float*)d_in[11];  // (1,D)

    float* out = (float*)d_out;
    float* out_known = out;
    float* out_unk   = out + OUT_UNK;
    float* out_sem   = out + OUT_SEM;

    // 1. attention scores
    k_scores<<<B * P, 256>>>((const float4*)patch, (const float4*)query);
    // 2. domain projection (independent of scores)
    k_dom<<<B, 512>>>(gfeat, domW, domb);
    // 3. softmax + semantic tokens (written straight to output slice)
    k_tokens<<<dim3(B, 4), 128>>>(patch, out_sem);
    // 4. semantic projection (reads tokens from output slice)
    k_sem<<<dim3(64, H, 2), 256>>>(out_sem, semW, semb);
    // 5. prompt fill: known (360 MB) + unknown, one block per prompt row
    k_fill<<<16032, 512>>>((const float4*)kpre, (const float4*)ksuf,
                           (const float4*)upre, (const float4*)usuf,
                           (const float4*)ust,
                           (float4*)out_known, (float4*)out_unk);
}